// round 1
// baseline (speedup 1.0000x reference)
#include <cuda_runtime.h>
#include <math.h>

// Problem constants
#define BB 4
#define TT 1024
#define CC 1024
#define HH 16
#define HS 64
#define C3 3072
#define BHT (BB*HH)          // 64
#define NROWS (BB*HH*TT)     // 65536

// Scratch (device globals — no allocation allowed)
__device__ float g_qkv[(size_t)BB*TT*C3];        // 48 MB  [B,T,3C]
__device__ float g_probs[(size_t)BB*HH*TT*TT];   // 256 MB [B,H,T,T] scores->probs->mod
__device__ float g_ypre[(size_t)BB*TT*CC];       // 16 MB  [B,T,C] (heads concatenated)
__device__ float g_colsum[BB*HH*TT];             // 256 KB [B,H,T] raw column sums of probs

__device__ __forceinline__ float sigmoidf_(float x) { return 1.0f / (1.0f + expf(-x)); }
__device__ __forceinline__ float softplusf_(float x) {
    return fmaxf(x, 0.0f) + log1pf(expf(-fabsf(x)));
}

// ---------------------------------------------------------------------------
// init: zero colsum and the refractory part of d_out
// ---------------------------------------------------------------------------
__global__ void init_kernel(float* refout) {
    int i = blockIdx.x * blockDim.x + threadIdx.x;
    if (i < BB*HH*TT) g_colsum[i] = 0.0f;
    if (i < BB*TT)    refout[i]   = 0.0f;
}

// ---------------------------------------------------------------------------
// GEMM: Co[M,N] = A[M,K] @ Bm[K,N] + bias[N].  128x128 tile, BK=8, 256 thr, 8x8/thr
// M,N,K all multiples of tile sizes here.
// ---------------------------------------------------------------------------
__global__ void gemm128_kernel(const float* __restrict__ A,
                               const float* __restrict__ Bm,
                               const float* __restrict__ bias,
                               float* __restrict__ Co,
                               int M, int N, int K) {
    __shared__ float As[8][128];
    __shared__ float Bs[8][128];
    int tid = threadIdx.x;
    int tx = tid & 15, ty = tid >> 4;
    int m0 = blockIdx.y * 128, n0 = blockIdx.x * 128;
    float acc[8][8];
    #pragma unroll
    for (int a = 0; a < 8; a++)
        #pragma unroll
        for (int b = 0; b < 8; b++) acc[a][b] = 0.0f;

    int arow = tid >> 1, akb = (tid & 1) * 4;   // A loader: 128 rows x 8 k
    int bkk  = tid >> 5, bj  = (tid & 31) * 4;  // B loader: 8 k x 128 n

    for (int k0 = 0; k0 < K; k0 += 8) {
        float4 av = *(const float4*)(A + (size_t)(m0 + arow) * K + k0 + akb);
        float4 bv = *(const float4*)(Bm + (size_t)(k0 + bkk) * N + n0 + bj);
        As[akb+0][arow] = av.x; As[akb+1][arow] = av.y;
        As[akb+2][arow] = av.z; As[akb+3][arow] = av.w;
        *(float4*)&Bs[bkk][bj] = bv;
        __syncthreads();
        #pragma unroll
        for (int kk = 0; kk < 8; kk++) {
            float ra[8], rb[8];
            #pragma unroll
            for (int a = 0; a < 8; a++) ra[a] = As[kk][ty*8 + a];
            #pragma unroll
            for (int b = 0; b < 8; b++) rb[b] = Bs[kk][tx*8 + b];
            #pragma unroll
            for (int a = 0; a < 8; a++)
                #pragma unroll
                for (int b = 0; b < 8; b++) acc[a][b] += ra[a] * rb[b];
        }
        __syncthreads();
    }
    #pragma unroll
    for (int a = 0; a < 8; a++) {
        int m = m0 + ty*8 + a;
        #pragma unroll
        for (int b = 0; b < 8; b++) {
            int n = n0 + tx*8 + b;
            Co[(size_t)m * N + n] = acc[a][b] + bias[n];
        }
    }
}

// ---------------------------------------------------------------------------
// scores: S[b,h,q,k] = (q . k) * 1/sqrt(64) for lower-triangular 64x64 tiles
// ---------------------------------------------------------------------------
__global__ void scores_kernel() {
    int kt = blockIdx.x, qt = blockIdx.y, bh = blockIdx.z;
    if (kt > qt) return;
    int b = bh >> 4, h = bh & 15;
    __shared__ float Qs[64][65];
    __shared__ float Ks[64][65];
    int tid = threadIdx.x;
    #pragma unroll
    for (int s = 0; s < 16; s++) {
        int idx = tid + s * 256;
        int i = idx >> 6, d = idx & 63;
        Qs[i][d] = g_qkv[(size_t)(b*TT + qt*64 + i) * C3 + h*HS + d];
        Ks[i][d] = g_qkv[(size_t)(b*TT + kt*64 + i) * C3 + CC + h*HS + d];
    }
    __syncthreads();
    int tx = tid & 15, ty = tid >> 4;
    float acc[4][4];
    #pragma unroll
    for (int a=0;a<4;a++) { acc[a][0]=0;acc[a][1]=0;acc[a][2]=0;acc[a][3]=0; }
    #pragma unroll 4
    for (int d = 0; d < 64; d++) {
        float rq[4], rk[4];
        #pragma unroll
        for (int a = 0; a < 4; a++) rq[a] = Qs[ty*4 + a][d];
        #pragma unroll
        for (int b2 = 0; b2 < 4; b2++) rk[b2] = Ks[tx*4 + b2][d];
        #pragma unroll
        for (int a = 0; a < 4; a++)
            #pragma unroll
            for (int b2 = 0; b2 < 4; b2++) acc[a][b2] += rq[a] * rk[b2];
    }
    size_t base = ((size_t)bh * TT + qt*64) * TT + kt*64;
    #pragma unroll
    for (int a = 0; a < 4; a++)
        #pragma unroll
        for (int b2 = 0; b2 < 4; b2++)
            g_probs[base + (size_t)(ty*4 + a) * TT + tx*4 + b2] = acc[a][b2] * 0.125f;
}

// ---------------------------------------------------------------------------
// softmax: per row (b,h,q), causal (k<=q), writes zeros for k>q. 128 threads.
// ---------------------------------------------------------------------------
__global__ void softmax_kernel() {
    int r = blockIdx.x;            // bh*1024 + q
    int q = r & (TT - 1);
    int tid = threadIdx.x;
    size_t base = (size_t)r * TT;
    __shared__ float red[128];
    float sv[8];
    float mx = -1e30f;
    #pragma unroll
    for (int i = 0; i < 8; i++) {
        int k = tid + i * 128;
        float s = (k <= q) ? g_probs[base + k] : -1e30f;
        sv[i] = s;
        mx = fmaxf(mx, s);
    }
    red[tid] = mx; __syncthreads();
    for (int o = 64; o > 0; o >>= 1) { if (tid < o) red[tid] = fmaxf(red[tid], red[tid+o]); __syncthreads(); }
    mx = red[0]; __syncthreads();
    float sum = 0.0f;
    #pragma unroll
    for (int i = 0; i < 8; i++) {
        int k = tid + i * 128;
        float e = (k <= q) ? expf(sv[i] - mx) : 0.0f;
        sv[i] = e; sum += e;
    }
    red[tid] = sum; __syncthreads();
    for (int o = 64; o > 0; o >>= 1) { if (tid < o) red[tid] += red[tid+o]; __syncthreads(); }
    float inv = 1.0f / red[0];
    #pragma unroll
    for (int i = 0; i < 8; i++) g_probs[base + tid + i*128] = sv[i] * inv;
}

// ---------------------------------------------------------------------------
// colsum: g_colsum[bh,k] += sum over a 128-query chunk of probs
// ---------------------------------------------------------------------------
__global__ void colsum_kernel() {
    int qc = blockIdx.x, bh = blockIdx.y;
    int tid = threadIdx.x;   // 256
    #pragma unroll
    for (int c = 0; c < 4; c++) {
        int k = tid + c * 256;
        size_t base = ((size_t)bh * TT + qc * 128) * TT + k;
        float s = 0.0f;
        #pragma unroll 4
        for (int q = 0; q < 128; q++) s += g_probs[base + (size_t)q * TT];
        atomicAdd(&g_colsum[bh * TT + k], s);
    }
}

// ---------------------------------------------------------------------------
// lif modulate + renormalize (in place on g_probs). per row, 128 threads.
// ---------------------------------------------------------------------------
__global__ void lifmod_kernel(const float* __restrict__ refst,
                              const float* __restrict__ threshold,
                              const float* __restrict__ leak,
                              const float* __restrict__ steepness,
                              const float* __restrict__ ref_strength,
                              const float* __restrict__ cross_w) {
    int r = blockIdx.x;
    int bh = r >> 10;
    int b = bh >> 4, h = bh & 15;
    int tid = threadIdx.x;
    float thr = fabsf(threshold[h]) * 0.1f;
    float lk  = sigmoidf_(leak[h]);
    float st  = softplusf_(steepness[h]);
    float rsp = softplusf_(ref_strength[h]);
    float cw  = sigmoidf_(cross_w[h]);
    size_t base = (size_t)r * TT;
    __shared__ float red[128];
    float mv[8];
    float sum = 0.0f;
    #pragma unroll
    for (int i = 0; i < 8; i++) {
        int k = tid + i * 128;
        float p = g_probs[base + k];
        float eff = thr + rsp * g_colsum[bh*TT + k] * (1.0f/1024.0f) + cw * refst[b*TT + k];
        float fire = sigmoidf_(st * (p - eff));
        float w = fire + lk * (1.0f - fire);
        float m = p * w;
        mv[i] = m; sum += m;
    }
    red[tid] = sum; __syncthreads();
    for (int o = 64; o > 0; o >>= 1) { if (tid < o) red[tid] += red[tid+o]; __syncthreads(); }
    float inv = 1.0f / (red[0] + 1e-8f);
    #pragma unroll
    for (int i = 0; i < 8; i++) g_probs[base + tid + i*128] = mv[i] * inv;
}

// ---------------------------------------------------------------------------
// refractory output: refout[b,k] = (1/(H*T)) sum_{h,q} mod[b,h,q,k]
// ---------------------------------------------------------------------------
__global__ void refreduce_kernel(float* __restrict__ refout) {
    int qc = blockIdx.x, bh = blockIdx.y;
    int b = bh >> 4;
    int tid = threadIdx.x;  // 256
    #pragma unroll
    for (int c = 0; c < 4; c++) {
        int k = tid + c * 256;
        size_t base = ((size_t)bh * TT + qc * 128) * TT + k;
        float s = 0.0f;
        #pragma unroll 4
        for (int q = 0; q < 128; q++) s += g_probs[base + (size_t)q * TT];
        atomicAdd(&refout[b*TT + k], s * (1.0f / (16.0f * 1024.0f)));
    }
}

// ---------------------------------------------------------------------------
// y_pre = mod @ V  per (b,h), written in [B,T,C] layout (heads concatenated)
// ---------------------------------------------------------------------------
__global__ void modv_kernel() {
    int qt = blockIdx.x, bh = blockIdx.y;
    int b = bh >> 4, h = bh & 15;
    __shared__ float Ms[64][65];
    __shared__ float Vs[64][64];
    int tid = threadIdx.x;
    int tx = tid & 15, ty = tid >> 4;
    float acc[4][4];
    #pragma unroll
    for (int a=0;a<4;a++) { acc[a][0]=0;acc[a][1]=0;acc[a][2]=0;acc[a][3]=0; }
    for (int kt = 0; kt <= qt; kt++) {
        #pragma unroll
        for (int s = 0; s < 16; s++) {
            int idx = tid + s * 256;
            int i = idx >> 6, j = idx & 63;
            Ms[i][j] = g_probs[((size_t)bh * TT + qt*64 + i) * TT + kt*64 + j];
            Vs[i][j] = g_qkv[(size_t)(b*TT + kt*64 + i) * C3 + 2*CC + h*HS + j];
        }
        __syncthreads();
        #pragma unroll 4
        for (int k = 0; k < 64; k++) {
            float rm[4], rv[4];
            #pragma unroll
            for (int a = 0; a < 4; a++) rm[a] = Ms[ty*4 + a][k];
            #pragma unroll
            for (int b2 = 0; b2 < 4; b2++) rv[b2] = Vs[k][tx*4 + b2];
            #pragma unroll
            for (int a = 0; a < 4; a++)
                #pragma unroll
                for (int b2 = 0; b2 < 4; b2++) acc[a][b2] += rm[a] * rv[b2];
        }
        __syncthreads();
    }
    #pragma unroll
    for (int a = 0; a < 4; a++) {
        int q = qt*64 + ty*4 + a;
        #pragma unroll
        for (int b2 = 0; b2 < 4; b2++)
            g_ypre[(size_t)(b*TT + q) * CC + h*HS + tx*4 + b2] = acc[a][b2];
    }
}

// ---------------------------------------------------------------------------
// launch
// ---------------------------------------------------------------------------
extern "C" void kernel_launch(void* const* d_in, const int* in_sizes, int n_in,
                              void* d_out, int out_size) {
    const float* x      = (const float*)d_in[0];
    const float* refst  = (const float*)d_in[1];
    const float* W_attn = (const float*)d_in[2];
    const float* b_attn = (const float*)d_in[3];
    const float* W_proj = (const float*)d_in[4];
    const float* b_proj = (const float*)d_in[5];
    const float* thr    = (const float*)d_in[6];
    const float* leak   = (const float*)d_in[7];
    const float* steep  = (const float*)d_in[8];
    const float* refstr = (const float*)d_in[9];
    const float* crossw = (const float*)d_in[10];

    float* y_out   = (float*)d_out;                      // [B,T,C]
    float* ref_out = (float*)d_out + (size_t)BB*TT*CC;   // [B,T]

    float* qkv  = nullptr;  cudaGetSymbolAddress((void**)&qkv,  g_qkv);
    float* ypre = nullptr;  cudaGetSymbolAddress((void**)&ypre, g_ypre);

    // 0. init
    init_kernel<<<(BB*HH*TT + 255)/256, 256>>>(ref_out);
    // 1. qkv = x @ W_attn + b_attn   [4096,3072]
    gemm128_kernel<<<dim3(C3/128, (BB*TT)/128), 256>>>(x, W_attn, b_attn, qkv, BB*TT, C3, CC);
    // 2. scores (causal tiles)
    scores_kernel<<<dim3(TT/64, TT/64, BHT), 256>>>();
    // 3. softmax per row
    softmax_kernel<<<NROWS, 128>>>();
    // 4. column sums of probs
    colsum_kernel<<<dim3(TT/128, BHT), 256>>>();
    // 5. LIF modulation + renormalize (in place)
    lifmod_kernel<<<NROWS, 128>>>(refst, thr, leak, steep, refstr, crossw);
    // 6. new refractory state
    refreduce_kernel<<<dim3(TT/128, BHT), 256>>>(ref_out);
    // 7. y_pre = mod @ V
    modv_kernel<<<dim3(TT/64, BHT), 256>>>();
    // 8. y = y_pre @ W_proj + b_proj
    gemm128_kernel<<<dim3(CC/128, (BB*TT)/128), 256>>>(ypre, W_proj, b_proj, y_out, BB*TT, CC, CC);
}

// round 2
// speedup vs baseline: 1.5106x; 1.5106x over previous
#include <cuda_runtime.h>
#include <math.h>
#include <stdint.h>

// Problem constants
#define BB 4
#define TT 1024
#define CC 1024
#define HH 16
#define HS 64
#define C3 3072
#define BHT (BB*HH)          // 64
#define NROWS (BB*HH*TT)     // 65536

// Scratch (device globals — no allocation allowed)
__device__ float g_qkv[(size_t)BB*TT*C3];        // 48 MB  [B,T,3C]
__device__ float g_probs[(size_t)BB*HH*TT*TT];   // 256 MB [B,H,T,T]
__device__ float g_ypre[(size_t)BB*TT*CC];       // 16 MB
__device__ float g_colsum[BB*HH*TT];             // 256 KB

__device__ __forceinline__ float sigmoidf_(float x) { return 1.0f / (1.0f + expf(-x)); }
__device__ __forceinline__ float softplusf_(float x) {
    return fmaxf(x, 0.0f) + log1pf(expf(-fabsf(x)));
}
__device__ __forceinline__ uint32_t f2tf32(float x) {
    uint32_t u; asm("cvt.rna.tf32.f32 %0, %1;" : "=r"(u) : "f"(x)); return u;
}

// ---------------------------------------------------------------------------
__global__ void init_kernel(float* refout) {
    int i = blockIdx.x * blockDim.x + threadIdx.x;
    if (i < BB*TT) refout[i] = 0.0f;
}

// ---------------------------------------------------------------------------
// TF32 tensor-core GEMM: Co[M,N] = A[M,K] @ Bm[K,N] + bias[N]
// 128x128 tile, BK=16, 8 warps (256 thr). Warp tile 64x32 via m16n8k8 mma.
// ---------------------------------------------------------------------------
#define AS_STRIDE 20
#define BS_STRIDE 136
__global__ __launch_bounds__(256, 2)
void gemm_tf32_kernel(const float* __restrict__ A,
                      const float* __restrict__ Bm,
                      const float* __restrict__ bias,
                      float* __restrict__ Co,
                      int M, int N, int K) {
    __shared__ float As[128 * AS_STRIDE];   // As[m][k], stride 20
    __shared__ float Bs[16 * BS_STRIDE];    // Bs[k][n], stride 136

    int tid = threadIdx.x;
    int wid = tid >> 5, lane = tid & 31;
    int g = lane >> 2, tig = lane & 3;
    int wm = wid & 1, wn = wid >> 1;        // warp grid 2 (m) x 4 (n)
    int m_base = wm * 64, n_base = wn * 32;
    int m0 = blockIdx.y * 128, n0 = blockIdx.x * 128;

    float acc[4][4][4];
    #pragma unroll
    for (int i = 0; i < 4; i++)
        #pragma unroll
        for (int j = 0; j < 4; j++)
            #pragma unroll
            for (int r = 0; r < 4; r++) acc[i][j][r] = 0.0f;

    for (int k0 = 0; k0 < K; k0 += 16) {
        // Load A tile: 128 rows x 16 k = 512 float4
        #pragma unroll
        for (int j = 0; j < 2; j++) {
            int f = tid * 2 + j;
            int row = f >> 2, kq = f & 3;
            float4 v = *(const float4*)(A + (size_t)(m0 + row) * K + k0 + kq * 4);
            float* d = &As[row * AS_STRIDE + kq * 4];
            d[0] = v.x; d[1] = v.y; d[2] = v.z; d[3] = v.w;
        }
        // Load B tile: 16 k x 128 n = 512 float4
        #pragma unroll
        for (int j = 0; j < 2; j++) {
            int f = tid * 2 + j;
            int k = f >> 5, nq = f & 31;
            float4 v = *(const float4*)(Bm + (size_t)(k0 + k) * N + n0 + nq * 4);
            float* d = &Bs[k * BS_STRIDE + nq * 4];
            d[0] = v.x; d[1] = v.y; d[2] = v.z; d[3] = v.w;
        }
        __syncthreads();

        #pragma unroll
        for (int ks = 0; ks < 16; ks += 8) {
            uint32_t af[4][4], bf[4][2];
            #pragma unroll
            for (int mf = 0; mf < 4; mf++) {
                int r0 = m_base + mf * 16 + g;
                af[mf][0] = f2tf32(As[(r0    ) * AS_STRIDE + ks + tig    ]);
                af[mf][1] = f2tf32(As[(r0 + 8) * AS_STRIDE + ks + tig    ]);
                af[mf][2] = f2tf32(As[(r0    ) * AS_STRIDE + ks + tig + 4]);
                af[mf][3] = f2tf32(As[(r0 + 8) * AS_STRIDE + ks + tig + 4]);
            }
            #pragma unroll
            for (int nf = 0; nf < 4; nf++) {
                int c0 = n_base + nf * 8 + g;
                bf[nf][0] = f2tf32(Bs[(ks + tig    ) * BS_STRIDE + c0]);
                bf[nf][1] = f2tf32(Bs[(ks + tig + 4) * BS_STRIDE + c0]);
            }
            #pragma unroll
            for (int mf = 0; mf < 4; mf++)
                #pragma unroll
                for (int nf = 0; nf < 4; nf++) {
                    asm volatile(
                        "mma.sync.aligned.m16n8k8.row.col.f32.tf32.tf32.f32 "
                        "{%0,%1,%2,%3}, {%4,%5,%6,%7}, {%8,%9}, {%0,%1,%2,%3};\n"
                        : "+f"(acc[mf][nf][0]), "+f"(acc[mf][nf][1]),
                          "+f"(acc[mf][nf][2]), "+f"(acc[mf][nf][3])
                        : "r"(af[mf][0]), "r"(af[mf][1]), "r"(af[mf][2]), "r"(af[mf][3]),
                          "r"(bf[nf][0]), "r"(bf[nf][1]));
                }
        }
        __syncthreads();
    }

    // Epilogue: c0: (g, 2tig) c1: (g, 2tig+1) c2: (g+8, 2tig) c3: (g+8, 2tig+1)
    #pragma unroll
    for (int mf = 0; mf < 4; mf++) {
        #pragma unroll
        for (int nf = 0; nf < 4; nf++) {
            int row = m0 + m_base + mf * 16 + g;
            int col = n0 + n_base + nf * 8 + tig * 2;
            float b0 = bias[col], b1 = bias[col + 1];
            Co[(size_t)row * N + col]           = acc[mf][nf][0] + b0;
            Co[(size_t)row * N + col + 1]       = acc[mf][nf][1] + b1;
            Co[(size_t)(row + 8) * N + col]     = acc[mf][nf][2] + b0;
            Co[(size_t)(row + 8) * N + col + 1] = acc[mf][nf][3] + b1;
        }
    }
}

// ---------------------------------------------------------------------------
// scores: lower-triangular 64x64 tiles of q.k / 8
// ---------------------------------------------------------------------------
__global__ void scores_kernel() {
    int kt = blockIdx.x, qt = blockIdx.y, bh = blockIdx.z;
    if (kt > qt) return;
    int b = bh >> 4, h = bh & 15;
    __shared__ float Qs[64][65];
    __shared__ float Ks[64][65];
    int tid = threadIdx.x;
    #pragma unroll
    for (int s = 0; s < 16; s++) {
        int idx = tid + s * 256;
        int i = idx >> 6, d = idx & 63;
        Qs[i][d] = g_qkv[(size_t)(b*TT + qt*64 + i) * C3 + h*HS + d];
        Ks[i][d] = g_qkv[(size_t)(b*TT + kt*64 + i) * C3 + CC + h*HS + d];
    }
    __syncthreads();
    int tx = tid & 15, ty = tid >> 4;
    float acc[4][4];
    #pragma unroll
    for (int a=0;a<4;a++) { acc[a][0]=0;acc[a][1]=0;acc[a][2]=0;acc[a][3]=0; }
    #pragma unroll 4
    for (int d = 0; d < 64; d++) {
        float rq[4], rk[4];
        #pragma unroll
        for (int a = 0; a < 4; a++) rq[a] = Qs[ty*4 + a][d];
        #pragma unroll
        for (int b2 = 0; b2 < 4; b2++) rk[b2] = Ks[tx*4 + b2][d];
        #pragma unroll
        for (int a = 0; a < 4; a++)
            #pragma unroll
            for (int b2 = 0; b2 < 4; b2++) acc[a][b2] += rq[a] * rk[b2];
    }
    size_t base = ((size_t)bh * TT + qt*64) * TT + kt*64;
    #pragma unroll
    for (int a = 0; a < 4; a++)
        #pragma unroll
        for (int b2 = 0; b2 < 4; b2++)
            g_probs[base + (size_t)(ty*4 + a) * TT + tx*4 + b2] = acc[a][b2] * 0.125f;
}

// ---------------------------------------------------------------------------
// softmax: per row, only writes k < nk = ((q>>6)+1)*64 (zeros for q<k<nk)
// ---------------------------------------------------------------------------
__global__ void softmax_kernel() {
    int r = blockIdx.x;
    int q = r & (TT - 1);
    int nk = ((q >> 6) + 1) * 64;
    int tid = threadIdx.x;
    size_t base = (size_t)r * TT;
    __shared__ float red[128];
    float sv[8];
    float mx = -1e30f;
    #pragma unroll
    for (int i = 0; i < 8; i++) {
        int k = tid + i * 128;
        float s = -1e30f;
        if (k <= q) s = g_probs[base + k];
        sv[i] = s;
        mx = fmaxf(mx, s);
    }
    red[tid] = mx; __syncthreads();
    for (int o = 64; o > 0; o >>= 1) { if (tid < o) red[tid] = fmaxf(red[tid], red[tid+o]); __syncthreads(); }
    mx = red[0]; __syncthreads();
    float sum = 0.0f;
    #pragma unroll
    for (int i = 0; i < 8; i++) {
        int k = tid + i * 128;
        float e = (k <= q) ? expf(sv[i] - mx) : 0.0f;
        sv[i] = e; sum += e;
    }
    red[tid] = sum; __syncthreads();
    for (int o = 64; o > 0; o >>= 1) { if (tid < o) red[tid] += red[tid+o]; __syncthreads(); }
    float inv = 1.0f / red[0];
    #pragma unroll
    for (int i = 0; i < 8; i++) {
        int k = tid + i * 128;
        if (k < nk) g_probs[base + k] = sv[i] * inv;
    }
}

// ---------------------------------------------------------------------------
// colsum: per-column triangular sum. grid (8 kchunks, bh), 128 thr.
// ---------------------------------------------------------------------------
__global__ void colsum_kernel() {
    int k = blockIdx.x * 128 + threadIdx.x;
    int bh = blockIdx.y;
    int qstart = k & ~63;
    size_t base = ((size_t)bh * TT) * TT + k;
    float s0 = 0.f, s1 = 0.f, s2 = 0.f, s3 = 0.f;
    int q = qstart;
    for (; q + 3 < TT; q += 4) {
        s0 += g_probs[base + (size_t)(q    ) * TT];
        s1 += g_probs[base + (size_t)(q + 1) * TT];
        s2 += g_probs[base + (size_t)(q + 2) * TT];
        s3 += g_probs[base + (size_t)(q + 3) * TT];
    }
    g_colsum[bh * TT + k] = (s0 + s1) + (s2 + s3);
}

// ---------------------------------------------------------------------------
// lif modulate + renormalize (in place). per row, only k < nk.
// ---------------------------------------------------------------------------
__global__ void lifmod_kernel(const float* __restrict__ refst,
                              const float* __restrict__ threshold,
                              const float* __restrict__ leak,
                              const float* __restrict__ steepness,
                              const float* __restrict__ ref_strength,
                              const float* __restrict__ cross_w) {
    int r = blockIdx.x;
    int bh = r >> 10;
    int q = r & (TT - 1);
    int nk = ((q >> 6) + 1) * 64;
    int b = bh >> 4, h = bh & 15;
    int tid = threadIdx.x;
    float thr = fabsf(threshold[h]) * 0.1f;
    float lk  = sigmoidf_(leak[h]);
    float st  = softplusf_(steepness[h]);
    float rsp = softplusf_(ref_strength[h]);
    float cw  = sigmoidf_(cross_w[h]);
    size_t base = (size_t)r * TT;
    __shared__ float red[128];
    float mv[8];
    float sum = 0.0f;
    #pragma unroll
    for (int i = 0; i < 8; i++) {
        int k = tid + i * 128;
        float m = 0.0f;
        if (k < nk) {
            float p = g_probs[base + k];
            float eff = thr + rsp * g_colsum[bh*TT + k] * (1.0f/1024.0f) + cw * refst[b*TT + k];
            float fire = sigmoidf_(st * (p - eff));
            float w = fire + lk * (1.0f - fire);
            m = p * w;
        }
        mv[i] = m; sum += m;
    }
    red[tid] = sum; __syncthreads();
    for (int o = 64; o > 0; o >>= 1) { if (tid < o) red[tid] += red[tid+o]; __syncthreads(); }
    float inv = 1.0f / (red[0] + 1e-8f);
    #pragma unroll
    for (int i = 0; i < 8; i++) {
        int k = tid + i * 128;
        if (k < nk) g_probs[base + k] = mv[i] * inv;
    }
}

// ---------------------------------------------------------------------------
// refractory output: per-column triangular sum of mod, atomicAdd over h.
// ---------------------------------------------------------------------------
__global__ void refreduce_kernel(float* __restrict__ refout) {
    int k = blockIdx.x * 128 + threadIdx.x;
    int bh = blockIdx.y;
    int b = bh >> 4;
    int qstart = k & ~63;
    size_t base = ((size_t)bh * TT) * TT + k;
    float s0 = 0.f, s1 = 0.f, s2 = 0.f, s3 = 0.f;
    int q = qstart;
    for (; q + 3 < TT; q += 4) {
        s0 += g_probs[base + (size_t)(q    ) * TT];
        s1 += g_probs[base + (size_t)(q + 1) * TT];
        s2 += g_probs[base + (size_t)(q + 2) * TT];
        s3 += g_probs[base + (size_t)(q + 3) * TT];
    }
    atomicAdd(&refout[b*TT + k], ((s0 + s1) + (s2 + s3)) * (1.0f / (16.0f * 1024.0f)));
}

// ---------------------------------------------------------------------------
// y_pre = mod @ V per (b,h), [B,T,C] layout
// ---------------------------------------------------------------------------
__global__ void modv_kernel() {
    int qt = blockIdx.x, bh = blockIdx.y;
    int b = bh >> 4, h = bh & 15;
    __shared__ float Ms[64][65];
    __shared__ float Vs[64][64];
    int tid = threadIdx.x;
    int tx = tid & 15, ty = tid >> 4;
    float acc[4][4];
    #pragma unroll
    for (int a=0;a<4;a++) { acc[a][0]=0;acc[a][1]=0;acc[a][2]=0;acc[a][3]=0; }
    for (int kt = 0; kt <= qt; kt++) {
        #pragma unroll
        for (int s = 0; s < 16; s++) {
            int idx = tid + s * 256;
            int i = idx >> 6, j = idx & 63;
            Ms[i][j] = g_probs[((size_t)bh * TT + qt*64 + i) * TT + kt*64 + j];
            Vs[i][j] = g_qkv[(size_t)(b*TT + kt*64 + i) * C3 + 2*CC + h*HS + j];
        }
        __syncthreads();
        #pragma unroll 4
        for (int k = 0; k < 64; k++) {
            float rm[4], rv[4];
            #pragma unroll
            for (int a = 0; a < 4; a++) rm[a] = Ms[ty*4 + a][k];
            #pragma unroll
            for (int b2 = 0; b2 < 4; b2++) rv[b2] = Vs[k][tx*4 + b2];
            #pragma unroll
            for (int a = 0; a < 4; a++)
                #pragma unroll
                for (int b2 = 0; b2 < 4; b2++) acc[a][b2] += rm[a] * rv[b2];
        }
        __syncthreads();
    }
    #pragma unroll
    for (int a = 0; a < 4; a++) {
        int q = qt*64 + ty*4 + a;
        #pragma unroll
        for (int b2 = 0; b2 < 4; b2++)
            g_ypre[(size_t)(b*TT + q) * CC + h*HS + tx*4 + b2] = acc[a][b2];
    }
}

// ---------------------------------------------------------------------------
extern "C" void kernel_launch(void* const* d_in, const int* in_sizes, int n_in,
                              void* d_out, int out_size) {
    const float* x      = (const float*)d_in[0];
    const float* refst  = (const float*)d_in[1];
    const float* W_attn = (const float*)d_in[2];
    const float* b_attn = (const float*)d_in[3];
    const float* W_proj = (const float*)d_in[4];
    const float* b_proj = (const float*)d_in[5];
    const float* thr    = (const float*)d_in[6];
    const float* leak   = (const float*)d_in[7];
    const float* steep  = (const float*)d_in[8];
    const float* refstr = (const float*)d_in[9];
    const float* crossw = (const float*)d_in[10];

    float* y_out   = (float*)d_out;
    float* ref_out = (float*)d_out + (size_t)BB*TT*CC;

    float* qkv  = nullptr;  cudaGetSymbolAddress((void**)&qkv,  g_qkv);
    float* ypre = nullptr;  cudaGetSymbolAddress((void**)&ypre, g_ypre);

    init_kernel<<<(BB*TT + 255)/256, 256>>>(ref_out);
    gemm_tf32_kernel<<<dim3(C3/128, (BB*TT)/128), 256>>>(x, W_attn, b_attn, qkv, BB*TT, C3, CC);
    scores_kernel<<<dim3(TT/64, TT/64, BHT), 256>>>();
    softmax_kernel<<<NROWS, 128>>>();
    colsum_kernel<<<dim3(TT/128, BHT), 128>>>();
    lifmod_kernel<<<NROWS, 128>>>(refst, thr, leak, steep, refstr, crossw);
    refreduce_kernel<<<dim3(TT/128, BHT), 128>>>(ref_out);
    modv_kernel<<<dim3(TT/64, BHT), 256>>>();
    gemm_tf32_kernel<<<dim3(CC/128, (BB*TT)/128), 256>>>(ypre, W_proj, b_proj, y_out, BB*TT, CC, CC);
}

// round 3
// speedup vs baseline: 2.0002x; 1.3241x over previous
#include <cuda_runtime.h>
#include <math.h>
#include <stdint.h>

#define BB 4
#define TT 1024
#define CC 1024
#define HH 16
#define HS 64
#define C3 3072
#define BHT (BB*HH)          // 64
#define NROWS (BB*HH*TT)     // 65536

// Scratch (device globals — no allocation allowed)
__device__ float g_qkv[(size_t)BB*TT*C3];        // 48 MB  [B,T,3C]
__device__ float g_probs[(size_t)BB*HH*TT*TT];   // 256 MB [B,H,T,T] exp-scores -> mod
__device__ float g_ypre[(size_t)BB*TT*CC];       // 16 MB
__device__ float g_colsum[BB*HH*TT];             // 256 KB
__device__ float g_rowinv[NROWS];                // 256 KB  1/rowsum per (b,h,q)

__device__ __forceinline__ float sigmoidf_(float x) { return 1.0f / (1.0f + expf(-x)); }
__device__ __forceinline__ float softplusf_(float x) {
    return fmaxf(x, 0.0f) + log1pf(expf(-fabsf(x)));
}
__device__ __forceinline__ uint32_t f2tf32(float x) {
    uint32_t u; asm("cvt.rna.tf32.f32 %0, %1;" : "=r"(u) : "f"(x)); return u;
}
__device__ __forceinline__ void mma_tf32(float* c, const uint32_t* a, uint32_t b0, uint32_t b1) {
    asm volatile("mma.sync.aligned.m16n8k8.row.col.f32.tf32.tf32.f32 "
        "{%0,%1,%2,%3}, {%4,%5,%6,%7}, {%8,%9}, {%0,%1,%2,%3};\n"
        : "+f"(c[0]), "+f"(c[1]), "+f"(c[2]), "+f"(c[3])
        : "r"(a[0]), "r"(a[1]), "r"(a[2]), "r"(a[3]), "r"(b0), "r"(b1));
}

// ---------------------------------------------------------------------------
__global__ void init_kernel(float* refout) {
    int i = blockIdx.x * blockDim.x + threadIdx.x;
    if (i < BB*TT) refout[i] = 0.0f;
}

// ---------------------------------------------------------------------------
// TF32 tensor-core GEMM: Co[M,N] = A[M,K] @ Bm[K,N] + bias[N]
// ---------------------------------------------------------------------------
#define AS_STRIDE 20
#define BS_STRIDE 136
__global__ __launch_bounds__(256, 2)
void gemm_tf32_kernel(const float* __restrict__ A,
                      const float* __restrict__ Bm,
                      const float* __restrict__ bias,
                      float* __restrict__ Co,
                      int M, int N, int K) {
    __shared__ float As[128 * AS_STRIDE];
    __shared__ float Bs[16 * BS_STRIDE];

    int tid = threadIdx.x;
    int wid = tid >> 5, lane = tid & 31;
    int g = lane >> 2, tig = lane & 3;
    int wm = wid & 1, wn = wid >> 1;
    int m_base = wm * 64, n_base = wn * 32;
    int m0 = blockIdx.y * 128, n0 = blockIdx.x * 128;

    float acc[4][4][4];
    #pragma unroll
    for (int i = 0; i < 4; i++)
        #pragma unroll
        for (int j = 0; j < 4; j++)
            #pragma unroll
            for (int r = 0; r < 4; r++) acc[i][j][r] = 0.0f;

    for (int k0 = 0; k0 < K; k0 += 16) {
        #pragma unroll
        for (int j = 0; j < 2; j++) {
            int f = tid * 2 + j;
            int row = f >> 2, kq = f & 3;
            float4 v = *(const float4*)(A + (size_t)(m0 + row) * K + k0 + kq * 4);
            float* d = &As[row * AS_STRIDE + kq * 4];
            d[0] = v.x; d[1] = v.y; d[2] = v.z; d[3] = v.w;
        }
        #pragma unroll
        for (int j = 0; j < 2; j++) {
            int f = tid * 2 + j;
            int k = f >> 5, nq = f & 31;
            float4 v = *(const float4*)(Bm + (size_t)(k0 + k) * N + n0 + nq * 4);
            float* d = &Bs[k * BS_STRIDE + nq * 4];
            d[0] = v.x; d[1] = v.y; d[2] = v.z; d[3] = v.w;
        }
        __syncthreads();

        #pragma unroll
        for (int ks = 0; ks < 16; ks += 8) {
            uint32_t af[4][4], bf[4][2];
            #pragma unroll
            for (int mf = 0; mf < 4; mf++) {
                int r0 = m_base + mf * 16 + g;
                af[mf][0] = f2tf32(As[(r0    ) * AS_STRIDE + ks + tig    ]);
                af[mf][1] = f2tf32(As[(r0 + 8) * AS_STRIDE + ks + tig    ]);
                af[mf][2] = f2tf32(As[(r0    ) * AS_STRIDE + ks + tig + 4]);
                af[mf][3] = f2tf32(As[(r0 + 8) * AS_STRIDE + ks + tig + 4]);
            }
            #pragma unroll
            for (int nf = 0; nf < 4; nf++) {
                int c0 = n_base + nf * 8 + g;
                bf[nf][0] = f2tf32(Bs[(ks + tig    ) * BS_STRIDE + c0]);
                bf[nf][1] = f2tf32(Bs[(ks + tig + 4) * BS_STRIDE + c0]);
            }
            #pragma unroll
            for (int mf = 0; mf < 4; mf++)
                #pragma unroll
                for (int nf = 0; nf < 4; nf++)
                    mma_tf32(acc[mf][nf], af[mf], bf[nf][0], bf[nf][1]);
        }
        __syncthreads();
    }

    #pragma unroll
    for (int mf = 0; mf < 4; mf++) {
        #pragma unroll
        for (int nf = 0; nf < 4; nf++) {
            int row = m0 + m_base + mf * 16 + g;
            int col = n0 + n_base + nf * 8 + tig * 2;
            float b0 = bias[col], b1 = bias[col + 1];
            Co[(size_t)row * N + col]           = acc[mf][nf][0] + b0;
            Co[(size_t)row * N + col + 1]       = acc[mf][nf][1] + b1;
            Co[(size_t)(row + 8) * N + col]     = acc[mf][nf][2] + b0;
            Co[(size_t)(row + 8) * N + col + 1] = acc[mf][nf][3] + b1;
        }
    }
}

// ---------------------------------------------------------------------------
// scores + exp + rowsum: block = (qt strip, bh). TF32 mma with hi/lo split.
// Writes e = exp(score/8) (causal-masked zeros in diag tile) and 1/rowsum.
// ---------------------------------------------------------------------------
__global__ __launch_bounds__(128, 2)
void scores_exp_kernel() {
    int qt = (int)gridDim.x - 1 - (int)blockIdx.x;   // heavy blocks first
    int bh = blockIdx.y;
    int b = bh >> 4, h = bh & 15;
    __shared__ float Qs[64][68];
    __shared__ float Ks[64][68];
    int tid = threadIdx.x;
    int w = tid >> 5, lane = tid & 31;
    int g = lane >> 2, tig = lane & 3;

    // load Q tile [64 x 64]
    {
        const float* src = g_qkv + (size_t)(b*TT + qt*64)*C3 + h*HS;
        #pragma unroll
        for (int s = 0; s < 8; s++) {
            int f = tid + s*128;
            int row = f >> 4, c4 = f & 15;
            float4 v = *(const float4*)(src + (size_t)row*C3 + c4*4);
            *(float4*)&Qs[row][c4*4] = v;
        }
    }
    __syncthreads();

    // persistent Q fragments, hi/lo split
    uint32_t qh[8][4], ql[8][4];
    #pragma unroll
    for (int ks = 0; ks < 8; ks++) {
        #pragma unroll
        for (int i = 0; i < 4; i++) {
            int rr = w*16 + g + (i & 1)*8;
            int cc = ks*8 + tig + (i >> 1)*4;
            float v = Qs[rr][cc];
            uint32_t hi = f2tf32(v);
            qh[ks][i] = hi;
            ql[ks][i] = f2tf32(v - __uint_as_float(hi));
        }
    }

    float rs0 = 0.f, rs1 = 0.f;
    int lrow0 = w*16 + g, lrow1 = lrow0 + 8;

    for (int kt = 0; kt <= qt; kt++) {
        __syncthreads();
        const float* src = g_qkv + (size_t)(b*TT + kt*64)*C3 + CC + h*HS;
        #pragma unroll
        for (int s = 0; s < 8; s++) {
            int f = tid + s*128;
            int row = f >> 4, c4 = f & 15;
            float4 v = *(const float4*)(src + (size_t)row*C3 + c4*4);
            *(float4*)&Ks[row][c4*4] = v;
        }
        __syncthreads();

        #pragma unroll
        for (int nf = 0; nf < 8; nf++) {
            float acc[4] = {0.f, 0.f, 0.f, 0.f};
            #pragma unroll
            for (int ks = 0; ks < 8; ks++) {
                float b0f = Ks[nf*8 + g][ks*8 + tig];
                float b1f = Ks[nf*8 + g][ks*8 + tig + 4];
                uint32_t b0h = f2tf32(b0f), b1h = f2tf32(b1f);
                uint32_t b0l = f2tf32(b0f - __uint_as_float(b0h));
                uint32_t b1l = f2tf32(b1f - __uint_as_float(b1h));
                mma_tf32(acc, qh[ks], b0h, b1h);
                mma_tf32(acc, qh[ks], b0l, b1l);
                mma_tf32(acc, ql[ks], b0h, b1h);
            }
            int lcol = nf*8 + tig*2;
            float e00 = __expf(acc[0]*0.125f);
            float e01 = __expf(acc[1]*0.125f);
            float e10 = __expf(acc[2]*0.125f);
            float e11 = __expf(acc[3]*0.125f);
            if (kt == qt) {
                if (lcol     > lrow0) e00 = 0.f;
                if (lcol + 1 > lrow0) e01 = 0.f;
                if (lcol     > lrow1) e10 = 0.f;
                if (lcol + 1 > lrow1) e11 = 0.f;
            }
            rs0 += e00 + e01; rs1 += e10 + e11;
            size_t base = ((size_t)bh*TT + qt*64 + lrow0)*TT + kt*64 + lcol;
            *(float2*)&g_probs[base]          = make_float2(e00, e01);
            *(float2*)&g_probs[base + 8*TT]   = make_float2(e10, e11);
        }
    }

    #pragma unroll
    for (int o = 1; o < 4; o <<= 1) {
        rs0 += __shfl_xor_sync(0xffffffffu, rs0, o);
        rs1 += __shfl_xor_sync(0xffffffffu, rs1, o);
    }
    if (tig == 0) {
        int r = bh*TT + qt*64 + lrow0;
        g_rowinv[r]     = 1.0f / rs0;
        g_rowinv[r + 8] = 1.0f / rs1;
    }
}

// ---------------------------------------------------------------------------
// colsum of normalized probs: colsum[bh,k] = sum_q e[q,k] * rowinv[q]
// ---------------------------------------------------------------------------
__global__ void colsum_kernel() {
    int k = blockIdx.x * 128 + threadIdx.x;
    int bh = blockIdx.y;
    int qstart = k & ~63;
    size_t base = ((size_t)bh * TT) * TT + k;
    const float* inv = g_rowinv + bh * TT;
    float s0 = 0.f, s1 = 0.f, s2 = 0.f, s3 = 0.f;
    for (int q = qstart; q < TT; q += 4) {
        s0 += g_probs[base + (size_t)(q    ) * TT] * inv[q];
        s1 += g_probs[base + (size_t)(q + 1) * TT] * inv[q + 1];
        s2 += g_probs[base + (size_t)(q + 2) * TT] * inv[q + 2];
        s3 += g_probs[base + (size_t)(q + 3) * TT] * inv[q + 3];
    }
    g_colsum[bh * TT + k] = (s0 + s1) + (s2 + s3);
}

// ---------------------------------------------------------------------------
// lif modulate + renormalize: p = e * rowinv, then mod, in place on g_probs
// ---------------------------------------------------------------------------
__global__ void lifmod_kernel(const float* __restrict__ refst,
                              const float* __restrict__ threshold,
                              const float* __restrict__ leak,
                              const float* __restrict__ steepness,
                              const float* __restrict__ ref_strength,
                              const float* __restrict__ cross_w) {
    int r = blockIdx.x;
    int bh = r >> 10;
    int q = r & (TT - 1);
    int nk = ((q >> 6) + 1) * 64;
    int b = bh >> 4, h = bh & 15;
    int tid = threadIdx.x;
    float thr = fabsf(threshold[h]) * 0.1f;
    float lk  = sigmoidf_(leak[h]);
    float st  = softplusf_(steepness[h]);
    float rsp = softplusf_(ref_strength[h]);
    float cw  = sigmoidf_(cross_w[h]);
    float rinv = g_rowinv[r];
    size_t base = (size_t)r * TT;
    __shared__ float red[128];
    float mv[8];
    float sum = 0.0f;
    #pragma unroll
    for (int i = 0; i < 8; i++) {
        int k = tid + i * 128;
        float m = 0.0f;
        if (k < nk) {
            float p = g_probs[base + k] * rinv;
            float eff = thr + rsp * g_colsum[bh*TT + k] * (1.0f/1024.0f) + cw * refst[b*TT + k];
            float fire = sigmoidf_(st * (p - eff));
            float w = fire + lk * (1.0f - fire);
            m = p * w;
        }
        mv[i] = m; sum += m;
    }
    red[tid] = sum; __syncthreads();
    for (int o = 64; o > 0; o >>= 1) { if (tid < o) red[tid] += red[tid+o]; __syncthreads(); }
    float invs = 1.0f / (red[0] + 1e-8f);
    #pragma unroll
    for (int i = 0; i < 8; i++) {
        int k = tid + i * 128;
        if (k < nk) g_probs[base + k] = mv[i] * invs;
    }
}

// ---------------------------------------------------------------------------
// y_pre = mod @ V (TF32 mma, hi/lo split) + fused refractory column reduce
// ---------------------------------------------------------------------------
__global__ __launch_bounds__(128, 2)
void modv_kernel(float* __restrict__ refout) {
    int qt = (int)gridDim.x - 1 - (int)blockIdx.x;
    int bh = blockIdx.y;
    int b = bh >> 4, h = bh & 15;
    __shared__ float Ms[64][68];
    __shared__ float Vs[64][72];
    int tid = threadIdx.x;
    int w = tid >> 5, lane = tid & 31;
    int g = lane >> 2, tig = lane & 3;

    float acc[8][4];
    #pragma unroll
    for (int nf = 0; nf < 8; nf++)
        #pragma unroll
        for (int i = 0; i < 4; i++) acc[nf][i] = 0.0f;

    for (int kt = 0; kt <= qt; kt++) {
        __syncthreads();
        {
            const float* msrc = g_probs + ((size_t)bh*TT + qt*64)*TT + kt*64;
            const float* vsrc = g_qkv + (size_t)(b*TT + kt*64)*C3 + 2*CC + h*HS;
            #pragma unroll
            for (int s = 0; s < 8; s++) {
                int f = tid + s*128;
                int row = f >> 4, c4 = f & 15;
                float4 mv = *(const float4*)(msrc + (size_t)row*TT + c4*4);
                *(float4*)&Ms[row][c4*4] = mv;
                float4 vv = *(const float4*)(vsrc + (size_t)row*C3 + c4*4);
                *(float4*)&Vs[row][c4*4] = vv;
            }
        }
        __syncthreads();

        // fused refractory column sums over this tile's 64 q rows
        if (tid < 64) {
            float s = 0.0f;
            #pragma unroll 8
            for (int i = 0; i < 64; i++) s += Ms[i][tid];
            atomicAdd(&refout[b*TT + kt*64 + tid], s * (1.0f / 16384.0f));
        }

        #pragma unroll
        for (int ks = 0; ks < 8; ks++) {
            uint32_t ah[4], al[4];
            #pragma unroll
            for (int i = 0; i < 4; i++) {
                float v = Ms[w*16 + g + (i & 1)*8][ks*8 + tig + (i >> 1)*4];
                uint32_t hi = f2tf32(v);
                ah[i] = hi;
                al[i] = f2tf32(v - __uint_as_float(hi));
            }
            #pragma unroll
            for (int nf = 0; nf < 8; nf++) {
                float b0f = Vs[ks*8 + tig][nf*8 + g];
                float b1f = Vs[ks*8 + tig + 4][nf*8 + g];
                uint32_t b0h = f2tf32(b0f), b1h = f2tf32(b1f);
                uint32_t b0l = f2tf32(b0f - __uint_as_float(b0h));
                uint32_t b1l = f2tf32(b1f - __uint_as_float(b1h));
                mma_tf32(acc[nf], ah, b0h, b1h);
                mma_tf32(acc[nf], ah, b0l, b1l);
                mma_tf32(acc[nf], al, b0h, b1h);
            }
        }
    }

    #pragma unroll
    for (int nf = 0; nf < 8; nf++) {
        int row = qt*64 + w*16 + g;
        int col = nf*8 + tig*2;
        float* dst = g_ypre + (size_t)(b*TT + row)*CC + h*HS + col;
        *(float2*)dst            = make_float2(acc[nf][0], acc[nf][1]);
        *(float2*)(dst + 8*CC)   = make_float2(acc[nf][2], acc[nf][3]);
    }
}

// ---------------------------------------------------------------------------
extern "C" void kernel_launch(void* const* d_in, const int* in_sizes, int n_in,
                              void* d_out, int out_size) {
    const float* x      = (const float*)d_in[0];
    const float* refst  = (const float*)d_in[1];
    const float* W_attn = (const float*)d_in[2];
    const float* b_attn = (const float*)d_in[3];
    const float* W_proj = (const float*)d_in[4];
    const float* b_proj = (const float*)d_in[5];
    const float* thr    = (const float*)d_in[6];
    const float* leak   = (const float*)d_in[7];
    const float* steep  = (const float*)d_in[8];
    const float* refstr = (const float*)d_in[9];
    const float* crossw = (const float*)d_in[10];

    float* y_out   = (float*)d_out;
    float* ref_out = (float*)d_out + (size_t)BB*TT*CC;

    float* qkv  = nullptr;  cudaGetSymbolAddress((void**)&qkv,  g_qkv);
    float* ypre = nullptr;  cudaGetSymbolAddress((void**)&ypre, g_ypre);

    init_kernel<<<(BB*TT + 255)/256, 256>>>(ref_out);
    gemm_tf32_kernel<<<dim3(C3/128, (BB*TT)/128), 256>>>(x, W_attn, b_attn, qkv, BB*TT, C3, CC);
    scores_exp_kernel<<<dim3(TT/64, BHT), 128>>>();
    colsum_kernel<<<dim3(TT/128, BHT), 128>>>();
    lifmod_kernel<<<NROWS, 128>>>(refst, thr, leak, steep, refstr, crossw);
    modv_kernel<<<dim3(TT/64, BHT), 128>>>(ref_out);
    gemm_tf32_kernel<<<dim3(CC/128, (BB*TT)/128), 256>>>(ypre, W_proj, b_proj, y_out, BB*TT, CC, CC);
}

// round 4
// speedup vs baseline: 2.3420x; 1.1709x over previous
#include <cuda_runtime.h>
#include <math.h>
#include <stdint.h>

#define BB 4
#define TT 1024
#define CC 1024
#define HH 16
#define HS 64
#define C3 3072
#define BHT (BB*HH)          // 64
#define NROWS (BB*HH*TT)     // 65536

// Scratch (device globals — no allocation allowed)
__device__ float g_qkv[(size_t)BB*TT*C3];        // 48 MB  [B,T,3C]
__device__ float g_probs[(size_t)BB*HH*TT*TT];   // 256 MB [B,H,T,T] exp-scores -> mod
__device__ float g_ypre[(size_t)BB*TT*CC];       // 16 MB
__device__ float g_colsum[BHT*TT];               // 256 KB
__device__ float g_rowinv[NROWS];                // 256 KB  1/rowsum per (b,h,q)

__device__ __forceinline__ float sigmoidf_(float x) { return 1.0f / (1.0f + expf(-x)); }
__device__ __forceinline__ float softplusf_(float x) {
    return fmaxf(x, 0.0f) + log1pf(expf(-fabsf(x)));
}
__device__ __forceinline__ uint32_t f2tf32(float x) {
    uint32_t u; asm("cvt.rna.tf32.f32 %0, %1;" : "=r"(u) : "f"(x)); return u;
}
__device__ __forceinline__ void mma_tf32(float* c, const uint32_t* a, uint32_t b0, uint32_t b1) {
    asm volatile("mma.sync.aligned.m16n8k8.row.col.f32.tf32.tf32.f32 "
        "{%0,%1,%2,%3}, {%4,%5,%6,%7}, {%8,%9}, {%0,%1,%2,%3};\n"
        : "+f"(c[0]), "+f"(c[1]), "+f"(c[2]), "+f"(c[3])
        : "r"(a[0]), "r"(a[1]), "r"(a[2]), "r"(a[3]), "r"(b0), "r"(b1));
}

// ---------------------------------------------------------------------------
__global__ void init_kernel(float* refout) {
    int i = blockIdx.x * blockDim.x + threadIdx.x;
    if (i < BHT*TT) g_colsum[i] = 0.0f;
    if (i < BB*TT)  refout[i]   = 0.0f;
}

// ---------------------------------------------------------------------------
// TF32 tensor-core GEMM: Co[M,N] = A[M,K] @ Bm[K,N] + bias[N]
// ---------------------------------------------------------------------------
#define AS_STRIDE 20
#define BS_STRIDE 136
__global__ __launch_bounds__(256, 2)
void gemm_tf32_kernel(const float* __restrict__ A,
                      const float* __restrict__ Bm,
                      const float* __restrict__ bias,
                      float* __restrict__ Co,
                      int M, int N, int K) {
    __shared__ float As[128 * AS_STRIDE];
    __shared__ float Bs[16 * BS_STRIDE];

    int tid = threadIdx.x;
    int wid = tid >> 5, lane = tid & 31;
    int g = lane >> 2, tig = lane & 3;
    int wm = wid & 1, wn = wid >> 1;
    int m_base = wm * 64, n_base = wn * 32;
    int m0 = blockIdx.y * 128, n0 = blockIdx.x * 128;

    float acc[4][4][4];
    #pragma unroll
    for (int i = 0; i < 4; i++)
        #pragma unroll
        for (int j = 0; j < 4; j++)
            #pragma unroll
            for (int r = 0; r < 4; r++) acc[i][j][r] = 0.0f;

    for (int k0 = 0; k0 < K; k0 += 16) {
        #pragma unroll
        for (int j = 0; j < 2; j++) {
            int f = tid * 2 + j;
            int row = f >> 2, kq = f & 3;
            float4 v = *(const float4*)(A + (size_t)(m0 + row) * K + k0 + kq * 4);
            float* d = &As[row * AS_STRIDE + kq * 4];
            d[0] = v.x; d[1] = v.y; d[2] = v.z; d[3] = v.w;
        }
        #pragma unroll
        for (int j = 0; j < 2; j++) {
            int f = tid * 2 + j;
            int k = f >> 5, nq = f & 31;
            float4 v = *(const float4*)(Bm + (size_t)(k0 + k) * N + n0 + nq * 4);
            float* d = &Bs[k * BS_STRIDE + nq * 4];
            d[0] = v.x; d[1] = v.y; d[2] = v.z; d[3] = v.w;
        }
        __syncthreads();

        #pragma unroll
        for (int ks = 0; ks < 16; ks += 8) {
            uint32_t af[4][4], bf[4][2];
            #pragma unroll
            for (int mf = 0; mf < 4; mf++) {
                int r0 = m_base + mf * 16 + g;
                af[mf][0] = f2tf32(As[(r0    ) * AS_STRIDE + ks + tig    ]);
                af[mf][1] = f2tf32(As[(r0 + 8) * AS_STRIDE + ks + tig    ]);
                af[mf][2] = f2tf32(As[(r0    ) * AS_STRIDE + ks + tig + 4]);
                af[mf][3] = f2tf32(As[(r0 + 8) * AS_STRIDE + ks + tig + 4]);
            }
            #pragma unroll
            for (int nf = 0; nf < 4; nf++) {
                int c0 = n_base + nf * 8 + g;
                bf[nf][0] = f2tf32(Bs[(ks + tig    ) * BS_STRIDE + c0]);
                bf[nf][1] = f2tf32(Bs[(ks + tig + 4) * BS_STRIDE + c0]);
            }
            #pragma unroll
            for (int mf = 0; mf < 4; mf++)
                #pragma unroll
                for (int nf = 0; nf < 4; nf++)
                    mma_tf32(acc[mf][nf], af[mf], bf[nf][0], bf[nf][1]);
        }
        __syncthreads();
    }

    #pragma unroll
    for (int mf = 0; mf < 4; mf++) {
        #pragma unroll
        for (int nf = 0; nf < 4; nf++) {
            int row = m0 + m_base + mf * 16 + g;
            int col = n0 + n_base + nf * 8 + tig * 2;
            float b0 = bias[col], b1 = bias[col + 1];
            Co[(size_t)row * N + col]           = acc[mf][nf][0] + b0;
            Co[(size_t)row * N + col + 1]       = acc[mf][nf][1] + b1;
            Co[(size_t)(row + 8) * N + col]     = acc[mf][nf][2] + b0;
            Co[(size_t)(row + 8) * N + col + 1] = acc[mf][nf][3] + b1;
        }
    }
}

// ---------------------------------------------------------------------------
// scores + exp + rowsum. K tile pre-converted to TF32 hi/lo in smem.
// ---------------------------------------------------------------------------
__global__ __launch_bounds__(128, 4)
void scores_exp_kernel() {
    int qt = (int)gridDim.x - 1 - (int)blockIdx.x;   // heavy blocks first
    int bh = blockIdx.y;
    int b = bh >> 4, h = bh & 15;
    __shared__ float    Qs[64][68];
    __shared__ uint32_t KsH[64][68];
    __shared__ uint32_t KsL[64][68];
    int tid = threadIdx.x;
    int w = tid >> 5, lane = tid & 31;
    int g = lane >> 2, tig = lane & 3;

    // load Q tile [64 x 64]
    {
        const float* src = g_qkv + (size_t)(b*TT + qt*64)*C3 + h*HS;
        #pragma unroll
        for (int s = 0; s < 8; s++) {
            int f = tid + s*128;
            int row = f >> 4, c4 = f & 15;
            float4 v = *(const float4*)(src + (size_t)row*C3 + c4*4);
            *(float4*)&Qs[row][c4*4] = v;
        }
    }
    __syncthreads();

    // persistent Q fragments, hi/lo split
    uint32_t qh[8][4], ql[8][4];
    #pragma unroll
    for (int ks = 0; ks < 8; ks++) {
        #pragma unroll
        for (int i = 0; i < 4; i++) {
            int rr = w*16 + g + (i & 1)*8;
            int cc = ks*8 + tig + (i >> 1)*4;
            float v = Qs[rr][cc];
            uint32_t hi = f2tf32(v);
            qh[ks][i] = hi;
            ql[ks][i] = f2tf32(v - __uint_as_float(hi));
        }
    }

    float rs0 = 0.f, rs1 = 0.f;
    int lrow0 = w*16 + g, lrow1 = lrow0 + 8;

    for (int kt = 0; kt <= qt; kt++) {
        __syncthreads();
        const float* src = g_qkv + (size_t)(b*TT + kt*64)*C3 + CC + h*HS;
        #pragma unroll
        for (int s = 0; s < 8; s++) {
            int f = tid + s*128;
            int row = f >> 4, c4 = f & 15;
            float4 v = *(const float4*)(src + (size_t)row*C3 + c4*4);
            uint32_t h0 = f2tf32(v.x), h1 = f2tf32(v.y), h2 = f2tf32(v.z), h3 = f2tf32(v.w);
            KsH[row][c4*4+0] = h0; KsH[row][c4*4+1] = h1;
            KsH[row][c4*4+2] = h2; KsH[row][c4*4+3] = h3;
            KsL[row][c4*4+0] = f2tf32(v.x - __uint_as_float(h0));
            KsL[row][c4*4+1] = f2tf32(v.y - __uint_as_float(h1));
            KsL[row][c4*4+2] = f2tf32(v.z - __uint_as_float(h2));
            KsL[row][c4*4+3] = f2tf32(v.w - __uint_as_float(h3));
        }
        __syncthreads();

        #pragma unroll
        for (int nf = 0; nf < 8; nf++) {
            float acc[4] = {0.f, 0.f, 0.f, 0.f};
            #pragma unroll
            for (int ks = 0; ks < 8; ks++) {
                uint32_t b0h = KsH[nf*8 + g][ks*8 + tig];
                uint32_t b1h = KsH[nf*8 + g][ks*8 + tig + 4];
                uint32_t b0l = KsL[nf*8 + g][ks*8 + tig];
                uint32_t b1l = KsL[nf*8 + g][ks*8 + tig + 4];
                mma_tf32(acc, qh[ks], b0h, b1h);
                mma_tf32(acc, qh[ks], b0l, b1l);
                mma_tf32(acc, ql[ks], b0h, b1h);
            }
            int lcol = nf*8 + tig*2;
            float e00 = __expf(acc[0]*0.125f);
            float e01 = __expf(acc[1]*0.125f);
            float e10 = __expf(acc[2]*0.125f);
            float e11 = __expf(acc[3]*0.125f);
            if (kt == qt) {
                if (lcol     > lrow0) e00 = 0.f;
                if (lcol + 1 > lrow0) e01 = 0.f;
                if (lcol     > lrow1) e10 = 0.f;
                if (lcol + 1 > lrow1) e11 = 0.f;
            }
            rs0 += e00 + e01; rs1 += e10 + e11;
            size_t base = ((size_t)bh*TT + qt*64 + lrow0)*TT + kt*64 + lcol;
            *(float2*)&g_probs[base]          = make_float2(e00, e01);
            *(float2*)&g_probs[base + 8*TT]   = make_float2(e10, e11);
        }
    }

    #pragma unroll
    for (int o = 1; o < 4; o <<= 1) {
        rs0 += __shfl_xor_sync(0xffffffffu, rs0, o);
        rs1 += __shfl_xor_sync(0xffffffffu, rs1, o);
    }
    if (tig == 0) {
        int r = bh*TT + qt*64 + lrow0;
        g_rowinv[r]     = 1.0f / rs0;
        g_rowinv[r + 8] = 1.0f / rs1;
    }
}

// ---------------------------------------------------------------------------
// colsum: tiled 128x128 triangular, grid (kc, qc, bh). atomicAdd accumulate.
// ---------------------------------------------------------------------------
__global__ __launch_bounds__(128, 8)
void colsum_kernel() {
    int kc = blockIdx.x, qc = blockIdx.y, bh = blockIdx.z;
    if (qc < kc) return;
    int tid = threadIdx.x;
    int k = kc * 128 + tid;
    __shared__ float inv[128];
    inv[tid] = g_rowinv[bh*TT + qc*128 + tid];
    __syncthreads();
    int qlo = (qc == kc) ? ((k & ~63) - qc*128) : 0;   // local row start
    size_t base = ((size_t)bh*TT + qc*128) * TT + k;
    float s = 0.0f;
    #pragma unroll 4
    for (int q = qlo; q < 128; q++)
        s += g_probs[base + (size_t)q * TT] * inv[q];
    atomicAdd(&g_colsum[bh*TT + k], s);
}

// ---------------------------------------------------------------------------
// lif modulate + renormalize: p = e * rowinv, then mod, in place on g_probs
// ---------------------------------------------------------------------------
__global__ __launch_bounds__(128)
void lifmod_kernel(const float* __restrict__ refst,
                   const float* __restrict__ threshold,
                   const float* __restrict__ leak,
                   const float* __restrict__ steepness,
                   const float* __restrict__ ref_strength,
                   const float* __restrict__ cross_w) {
    int r = blockIdx.x;
    int bh = r >> 10;
    int q = r & (TT - 1);
    int nk = ((q >> 6) + 1) * 64;
    int b = bh >> 4, h = bh & 15;
    int tid = threadIdx.x;
    int wid = tid >> 5, lane = tid & 31;
    float thr = fabsf(threshold[h]) * 0.1f;
    float lk  = sigmoidf_(leak[h]);
    float st  = softplusf_(steepness[h]);
    float rsp = softplusf_(ref_strength[h]);
    float cw  = sigmoidf_(cross_w[h]);
    float rinv = g_rowinv[r];
    size_t base = (size_t)r * TT;
    float mv[8];
    float sum = 0.0f;
    #pragma unroll
    for (int i = 0; i < 2; i++) {
        int k = i * 512 + tid * 4;
        if (k < nk) {
            float4 p4 = *(const float4*)&g_probs[base + k];
            float4 c4 = *(const float4*)&g_colsum[bh*TT + k];
            float4 f4 = *(const float4*)(refst + b*TT + k);
            float pp[4] = {p4.x, p4.y, p4.z, p4.w};
            float cc[4] = {c4.x, c4.y, c4.z, c4.w};
            float ff[4] = {f4.x, f4.y, f4.z, f4.w};
            #pragma unroll
            for (int j = 0; j < 4; j++) {
                float p = pp[j] * rinv;
                float eff = thr + rsp * cc[j] * (1.0f/1024.0f) + cw * ff[j];
                float fire = sigmoidf_(st * (p - eff));
                float wgt = fire + lk * (1.0f - fire);
                float m = p * wgt;
                mv[i*4 + j] = m;
                sum += m;
            }
        } else {
            mv[i*4] = mv[i*4+1] = mv[i*4+2] = mv[i*4+3] = 0.0f;
        }
    }
    #pragma unroll
    for (int o = 16; o > 0; o >>= 1) sum += __shfl_xor_sync(0xffffffffu, sum, o);
    __shared__ float red[4];
    if (lane == 0) red[wid] = sum;
    __syncthreads();
    float invs = 1.0f / (red[0] + red[1] + red[2] + red[3] + 1e-8f);
    #pragma unroll
    for (int i = 0; i < 2; i++) {
        int k = i * 512 + tid * 4;
        if (k < nk) {
            float4 o4 = make_float4(mv[i*4]*invs, mv[i*4+1]*invs, mv[i*4+2]*invs, mv[i*4+3]*invs);
            *(float4*)&g_probs[base + k] = o4;
        }
    }
}

// ---------------------------------------------------------------------------
// y_pre = mod @ V (TF32 mma, hi/lo split, V pre-converted) + fused ref reduce
// ---------------------------------------------------------------------------
__global__ __launch_bounds__(128, 3)
void modv_kernel(float* __restrict__ refout) {
    int qt = (int)gridDim.x - 1 - (int)blockIdx.x;
    int bh = blockIdx.y;
    int b = bh >> 4, h = bh & 15;
    __shared__ float    Ms[64][68];
    __shared__ uint32_t VsH[64][68];
    __shared__ uint32_t VsL[64][68];
    int tid = threadIdx.x;
    int w = tid >> 5, lane = tid & 31;
    int g = lane >> 2, tig = lane & 3;

    float acc[8][4];
    #pragma unroll
    for (int nf = 0; nf < 8; nf++)
        #pragma unroll
        for (int i = 0; i < 4; i++) acc[nf][i] = 0.0f;

    for (int kt = 0; kt <= qt; kt++) {
        __syncthreads();
        {
            const float* msrc = g_probs + ((size_t)bh*TT + qt*64)*TT + kt*64;
            const float* vsrc = g_qkv + (size_t)(b*TT + kt*64)*C3 + 2*CC + h*HS;
            #pragma unroll
            for (int s = 0; s < 8; s++) {
                int f = tid + s*128;
                int row = f >> 4, c4 = f & 15;
                float4 mv = *(const float4*)(msrc + (size_t)row*TT + c4*4);
                *(float4*)&Ms[row][c4*4] = mv;
                float4 v = *(const float4*)(vsrc + (size_t)row*C3 + c4*4);
                uint32_t h0 = f2tf32(v.x), h1 = f2tf32(v.y), h2 = f2tf32(v.z), h3 = f2tf32(v.w);
                VsH[row][c4*4+0] = h0; VsH[row][c4*4+1] = h1;
                VsH[row][c4*4+2] = h2; VsH[row][c4*4+3] = h3;
                VsL[row][c4*4+0] = f2tf32(v.x - __uint_as_float(h0));
                VsL[row][c4*4+1] = f2tf32(v.y - __uint_as_float(h1));
                VsL[row][c4*4+2] = f2tf32(v.z - __uint_as_float(h2));
                VsL[row][c4*4+3] = f2tf32(v.w - __uint_as_float(h3));
            }
        }
        __syncthreads();

        // fused refractory column sums over this tile's 64 q rows
        if (tid < 64) {
            float s = 0.0f;
            #pragma unroll 8
            for (int i = 0; i < 64; i++) s += Ms[i][tid];
            atomicAdd(&refout[b*TT + kt*64 + tid], s * (1.0f / 16384.0f));
        }

        #pragma unroll
        for (int ks = 0; ks < 8; ks++) {
            uint32_t ah[4], al[4];
            #pragma unroll
            for (int i = 0; i < 4; i++) {
                float v = Ms[w*16 + g + (i & 1)*8][ks*8 + tig + (i >> 1)*4];
                uint32_t hi = f2tf32(v);
                ah[i] = hi;
                al[i] = f2tf32(v - __uint_as_float(hi));
            }
            #pragma unroll
            for (int nf = 0; nf < 8; nf++) {
                uint32_t b0h = VsH[ks*8 + tig][nf*8 + g];
                uint32_t b1h = VsH[ks*8 + tig + 4][nf*8 + g];
                uint32_t b0l = VsL[ks*8 + tig][nf*8 + g];
                uint32_t b1l = VsL[ks*8 + tig + 4][nf*8 + g];
                mma_tf32(acc[nf], ah, b0h, b1h);
                mma_tf32(acc[nf], ah, b0l, b1l);
                mma_tf32(acc[nf], al, b0h, b1h);
            }
        }
    }

    #pragma unroll
    for (int nf = 0; nf < 8; nf++) {
        int row = qt*64 + w*16 + g;
        int col = nf*8 + tig*2;
        float* dst = g_ypre + (size_t)(b*TT + row)*CC + h*HS + col;
        *(float2*)dst            = make_float2(acc[nf][0], acc[nf][1]);
        *(float2*)(dst + 8*CC)   = make_float2(acc[nf][2], acc[nf][3]);
    }
}

// ---------------------------------------------------------------------------
extern "C" void kernel_launch(void* const* d_in, const int* in_sizes, int n_in,
                              void* d_out, int out_size) {
    const float* x      = (const float*)d_in[0];
    const float* refst  = (const float*)d_in[1];
    const float* W_attn = (const float*)d_in[2];
    const float* b_attn = (const float*)d_in[3];
    const float* W_proj = (const float*)d_in[4];
    const float* b_proj = (const float*)d_in[5];
    const float* thr    = (const float*)d_in[6];
    const float* leak   = (const float*)d_in[7];
    const float* steep  = (const float*)d_in[8];
    const float* refstr = (const float*)d_in[9];
    const float* crossw = (const float*)d_in[10];

    float* y_out   = (float*)d_out;
    float* ref_out = (float*)d_out + (size_t)BB*TT*CC;

    float* qkv  = nullptr;  cudaGetSymbolAddress((void**)&qkv,  g_qkv);
    float* ypre = nullptr;  cudaGetSymbolAddress((void**)&ypre, g_ypre);

    init_kernel<<<(BHT*TT + 255)/256, 256>>>(ref_out);
    gemm_tf32_kernel<<<dim3(C3/128, (BB*TT)/128), 256>>>(x, W_attn, b_attn, qkv, BB*TT, C3, CC);
    scores_exp_kernel<<<dim3(TT/64, BHT), 128>>>();
    colsum_kernel<<<dim3(TT/128, TT/128, BHT), 128>>>();
    lifmod_kernel<<<NROWS, 128>>>(refst, thr, leak, steep, refstr, crossw);
    modv_kernel<<<dim3(TT/64, BHT), 128>>>(ref_out);
    gemm_tf32_kernel<<<dim3(CC/128, (BB*TT)/128), 256>>>(ypre, W_proj, b_proj, y_out, BB*TT, CC, CC);
}

// round 5
// speedup vs baseline: 2.5401x; 1.0846x over previous
#include <cuda_runtime.h>
#include <math.h>
#include <stdint.h>

#define BB 4
#define TT 1024
#define CC 1024
#define HH 16
#define HS 64
#define C3 3072
#define BHT (BB*HH)          // 64
#define NROWS (BB*HH*TT)     // 65536

// Scratch (device globals — no allocation allowed)
__device__ float g_qkv[(size_t)BB*TT*C3];        // 48 MB  [B,T,3C]
__device__ float g_probs[(size_t)BB*HH*TT*TT];   // 256 MB [B,H,T,T] exp-scores -> mod
__device__ float g_ypre[(size_t)BB*TT*CC];       // 16 MB
__device__ float g_colsum[BHT*TT];               // 256 KB
__device__ float g_rowinv[NROWS];                // 256 KB  1/rowsum per (b,h,q)

__device__ __forceinline__ float sigmoidf_(float x) { return 1.0f / (1.0f + expf(-x)); }
__device__ __forceinline__ float softplusf_(float x) {
    return fmaxf(x, 0.0f) + log1pf(expf(-fabsf(x)));
}
__device__ __forceinline__ uint32_t f2tf32(float x) {
    uint32_t u; asm("cvt.rna.tf32.f32 %0, %1;" : "=r"(u) : "f"(x)); return u;
}
__device__ __forceinline__ void mma_tf32(float* c, const uint32_t* a, uint32_t b0, uint32_t b1) {
    asm volatile("mma.sync.aligned.m16n8k8.row.col.f32.tf32.tf32.f32 "
        "{%0,%1,%2,%3}, {%4,%5,%6,%7}, {%8,%9}, {%0,%1,%2,%3};\n"
        : "+f"(c[0]), "+f"(c[1]), "+f"(c[2]), "+f"(c[3])
        : "r"(a[0]), "r"(a[1]), "r"(a[2]), "r"(a[3]), "r"(b0), "r"(b1));
}
__device__ __forceinline__ void cp_async16(void* smem_dst, const void* gsrc) {
    uint32_t s = (uint32_t)__cvta_generic_to_shared(smem_dst);
    asm volatile("cp.async.ca.shared.global [%0], [%1], 16;\n" :: "r"(s), "l"(gsrc));
}
#define CP_COMMIT() asm volatile("cp.async.commit_group;\n" ::: "memory")
#define CP_WAIT1()  asm volatile("cp.async.wait_group 1;\n" ::: "memory")
#define CP_WAIT0()  asm volatile("cp.async.wait_group 0;\n" ::: "memory")

// ---------------------------------------------------------------------------
__global__ void init_kernel(float* refout) {
    int i = blockIdx.x * blockDim.x + threadIdx.x;
    if (i < BHT*TT) g_colsum[i] = 0.0f;
    if (i < BB*TT)  refout[i]   = 0.0f;
}

// ---------------------------------------------------------------------------
// TF32 tensor-core GEMM, cp.async double-buffered (2-stage).
// Co[M,N] = A[M,K] @ Bm[K,N] + bias[N]
// ---------------------------------------------------------------------------
#define AS_STRIDE 20
#define BS_STRIDE 136
__global__ __launch_bounds__(256, 2)
void gemm_tf32_kernel(const float* __restrict__ A,
                      const float* __restrict__ Bm,
                      const float* __restrict__ bias,
                      float* __restrict__ Co,
                      int M, int N, int K) {
    __shared__ float As[2][128 * AS_STRIDE];
    __shared__ float Bs[2][16 * BS_STRIDE];

    int tid = threadIdx.x;
    int wid = tid >> 5, lane = tid & 31;
    int g = lane >> 2, tig = lane & 3;
    int wm = wid & 1, wn = wid >> 1;
    int m_base = wm * 64, n_base = wn * 32;
    int m0 = blockIdx.y * 128, n0 = blockIdx.x * 128;

    // loader indices
    int f0 = tid * 2, f1 = tid * 2 + 1;
    int ar0 = f0 >> 2, ak0 = (f0 & 3) * 4;
    int ar1 = f1 >> 2, ak1 = (f1 & 3) * 4;
    int bk0 = f0 >> 5, bn0 = (f0 & 31) * 4;
    int bk1 = f1 >> 5, bn1 = (f1 & 31) * 4;

    float acc[4][4][4];
    #pragma unroll
    for (int i = 0; i < 4; i++)
        #pragma unroll
        for (int j = 0; j < 4; j++)
            #pragma unroll
            for (int r = 0; r < 4; r++) acc[i][j][r] = 0.0f;

    int nt = K / 16;
    // prefetch tile 0
    {
        cp_async16(&As[0][ar0 * AS_STRIDE + ak0], A + (size_t)(m0 + ar0) * K + ak0);
        cp_async16(&As[0][ar1 * AS_STRIDE + ak1], A + (size_t)(m0 + ar1) * K + ak1);
        cp_async16(&Bs[0][bk0 * BS_STRIDE + bn0], Bm + (size_t)bk0 * N + n0 + bn0);
        cp_async16(&Bs[0][bk1 * BS_STRIDE + bn1], Bm + (size_t)bk1 * N + n0 + bn1);
        CP_COMMIT();
    }

    for (int t = 0; t < nt; t++) {
        int cur = t & 1, nxt = cur ^ 1;
        if (t + 1 < nt) {
            int k0 = (t + 1) * 16;
            cp_async16(&As[nxt][ar0 * AS_STRIDE + ak0], A + (size_t)(m0 + ar0) * K + k0 + ak0);
            cp_async16(&As[nxt][ar1 * AS_STRIDE + ak1], A + (size_t)(m0 + ar1) * K + k0 + ak1);
            cp_async16(&Bs[nxt][bk0 * BS_STRIDE + bn0], Bm + (size_t)(k0 + bk0) * N + n0 + bn0);
            cp_async16(&Bs[nxt][bk1 * BS_STRIDE + bn1], Bm + (size_t)(k0 + bk1) * N + n0 + bn1);
            CP_COMMIT();
            CP_WAIT1();
        } else {
            CP_WAIT0();
        }
        __syncthreads();

        const float* as = As[cur];
        const float* bs = Bs[cur];
        #pragma unroll
        for (int ks = 0; ks < 16; ks += 8) {
            uint32_t af[4][4], bf[4][2];
            #pragma unroll
            for (int mf = 0; mf < 4; mf++) {
                int r0 = m_base + mf * 16 + g;
                af[mf][0] = f2tf32(as[(r0    ) * AS_STRIDE + ks + tig    ]);
                af[mf][1] = f2tf32(as[(r0 + 8) * AS_STRIDE + ks + tig    ]);
                af[mf][2] = f2tf32(as[(r0    ) * AS_STRIDE + ks + tig + 4]);
                af[mf][3] = f2tf32(as[(r0 + 8) * AS_STRIDE + ks + tig + 4]);
            }
            #pragma unroll
            for (int nf = 0; nf < 4; nf++) {
                int c0 = n_base + nf * 8 + g;
                bf[nf][0] = f2tf32(bs[(ks + tig    ) * BS_STRIDE + c0]);
                bf[nf][1] = f2tf32(bs[(ks + tig + 4) * BS_STRIDE + c0]);
            }
            #pragma unroll
            for (int mf = 0; mf < 4; mf++)
                #pragma unroll
                for (int nf = 0; nf < 4; nf++)
                    mma_tf32(acc[mf][nf], af[mf], bf[nf][0], bf[nf][1]);
        }
        __syncthreads();
    }

    #pragma unroll
    for (int mf = 0; mf < 4; mf++) {
        #pragma unroll
        for (int nf = 0; nf < 4; nf++) {
            int row = m0 + m_base + mf * 16 + g;
            int col = n0 + n_base + nf * 8 + tig * 2;
            float b0 = bias[col], b1 = bias[col + 1];
            Co[(size_t)row * N + col]           = acc[mf][nf][0] + b0;
            Co[(size_t)row * N + col + 1]       = acc[mf][nf][1] + b1;
            Co[(size_t)(row + 8) * N + col]     = acc[mf][nf][2] + b0;
            Co[(size_t)(row + 8) * N + col + 1] = acc[mf][nf][3] + b1;
        }
    }
}

// ---------------------------------------------------------------------------
// scores + exp + rowsum + fused colsum. K tile pre-converted to TF32 hi/lo.
// ---------------------------------------------------------------------------
__global__ __launch_bounds__(128, 4)
void scores_exp_kernel() {
    int qt = (int)gridDim.x - 1 - (int)blockIdx.x;   // heavy blocks first
    int bh = blockIdx.y;
    int b = bh >> 4, h = bh & 15;
    __shared__ float    Qs[64][68];
    __shared__ uint32_t KsH[64][68];
    __shared__ uint32_t KsL[64][68];
    __shared__ float    sinv[64];
    int tid = threadIdx.x;
    int w = tid >> 5, lane = tid & 31;
    int g = lane >> 2, tig = lane & 3;

    // load Q tile [64 x 64]
    {
        const float* src = g_qkv + (size_t)(b*TT + qt*64)*C3 + h*HS;
        #pragma unroll
        for (int s = 0; s < 8; s++) {
            int f = tid + s*128;
            int row = f >> 4, c4 = f & 15;
            float4 v = *(const float4*)(src + (size_t)row*C3 + c4*4);
            *(float4*)&Qs[row][c4*4] = v;
        }
    }
    __syncthreads();

    // persistent Q fragments, hi/lo split
    uint32_t qh[8][4], ql[8][4];
    #pragma unroll
    for (int ks = 0; ks < 8; ks++) {
        #pragma unroll
        for (int i = 0; i < 4; i++) {
            int rr = w*16 + g + (i & 1)*8;
            int cc = ks*8 + tig + (i >> 1)*4;
            float v = Qs[rr][cc];
            uint32_t hi = f2tf32(v);
            qh[ks][i] = hi;
            ql[ks][i] = f2tf32(v - __uint_as_float(hi));
        }
    }

    float rs0 = 0.f, rs1 = 0.f;
    int lrow0 = w*16 + g, lrow1 = lrow0 + 8;

    for (int kt = 0; kt <= qt; kt++) {
        __syncthreads();
        const float* src = g_qkv + (size_t)(b*TT + kt*64)*C3 + CC + h*HS;
        #pragma unroll
        for (int s = 0; s < 8; s++) {
            int f = tid + s*128;
            int row = f >> 4, c4 = f & 15;
            float4 v = *(const float4*)(src + (size_t)row*C3 + c4*4);
            uint32_t h0 = f2tf32(v.x), h1 = f2tf32(v.y), h2 = f2tf32(v.z), h3 = f2tf32(v.w);
            KsH[row][c4*4+0] = h0; KsH[row][c4*4+1] = h1;
            KsH[row][c4*4+2] = h2; KsH[row][c4*4+3] = h3;
            KsL[row][c4*4+0] = f2tf32(v.x - __uint_as_float(h0));
            KsL[row][c4*4+1] = f2tf32(v.y - __uint_as_float(h1));
            KsL[row][c4*4+2] = f2tf32(v.z - __uint_as_float(h2));
            KsL[row][c4*4+3] = f2tf32(v.w - __uint_as_float(h3));
        }
        __syncthreads();

        #pragma unroll
        for (int nf = 0; nf < 8; nf++) {
            float acc[4] = {0.f, 0.f, 0.f, 0.f};
            #pragma unroll
            for (int ks = 0; ks < 8; ks++) {
                uint32_t b0h = KsH[nf*8 + g][ks*8 + tig];
                uint32_t b1h = KsH[nf*8 + g][ks*8 + tig + 4];
                uint32_t b0l = KsL[nf*8 + g][ks*8 + tig];
                uint32_t b1l = KsL[nf*8 + g][ks*8 + tig + 4];
                mma_tf32(acc, qh[ks], b0h, b1h);
                mma_tf32(acc, qh[ks], b0l, b1l);
                mma_tf32(acc, ql[ks], b0h, b1h);
            }
            int lcol = nf*8 + tig*2;
            float e00 = __expf(acc[0]*0.125f);
            float e01 = __expf(acc[1]*0.125f);
            float e10 = __expf(acc[2]*0.125f);
            float e11 = __expf(acc[3]*0.125f);
            if (kt == qt) {
                if (lcol     > lrow0) e00 = 0.f;
                if (lcol + 1 > lrow0) e01 = 0.f;
                if (lcol     > lrow1) e10 = 0.f;
                if (lcol + 1 > lrow1) e11 = 0.f;
            }
            rs0 += e00 + e01; rs1 += e10 + e11;
            size_t base = ((size_t)bh*TT + qt*64 + lrow0)*TT + kt*64 + lcol;
            *(float2*)&g_probs[base]          = make_float2(e00, e01);
            *(float2*)&g_probs[base + 8*TT]   = make_float2(e10, e11);
        }
    }

    #pragma unroll
    for (int o = 1; o < 4; o <<= 1) {
        rs0 += __shfl_xor_sync(0xffffffffu, rs0, o);
        rs1 += __shfl_xor_sync(0xffffffffu, rs1, o);
    }
    if (tig == 0) {
        int r = bh*TT + qt*64 + lrow0;
        float i0 = 1.0f / rs0, i1 = 1.0f / rs1;
        g_rowinv[r]     = i0;
        g_rowinv[r + 8] = i1;
        sinv[lrow0]     = i0;
        sinv[lrow1]     = i1;
    }
    __syncthreads();

    // fused colsum: own strip contribution, Σ_q e[q,k]*rowinv[q] (reads hit L2)
    int nk = (qt + 1) * 64;
    const float* strip = g_probs + ((size_t)bh*TT + qt*64)*TT;
    for (int k = tid; k < nk; k += 128) {
        float s0 = 0.f, s1 = 0.f, s2 = 0.f, s3 = 0.f;
        #pragma unroll
        for (int i = 0; i < 64; i += 4) {
            s0 += strip[(size_t)(i    ) * TT + k] * sinv[i    ];
            s1 += strip[(size_t)(i + 1) * TT + k] * sinv[i + 1];
            s2 += strip[(size_t)(i + 2) * TT + k] * sinv[i + 2];
            s3 += strip[(size_t)(i + 3) * TT + k] * sinv[i + 3];
        }
        atomicAdd(&g_colsum[bh*TT + k], (s0 + s1) + (s2 + s3));
    }
}

// ---------------------------------------------------------------------------
// lif modulate + renormalize: p = e * rowinv, then mod, in place on g_probs
// ---------------------------------------------------------------------------
__global__ __launch_bounds__(128)
void lifmod_kernel(const float* __restrict__ refst,
                   const float* __restrict__ threshold,
                   const float* __restrict__ leak,
                   const float* __restrict__ steepness,
                   const float* __restrict__ ref_strength,
                   const float* __restrict__ cross_w) {
    int r = blockIdx.x;
    int bh = r >> 10;
    int q = r & (TT - 1);
    int nk = ((q >> 6) + 1) * 64;
    int b = bh >> 4, h = bh & 15;
    int tid = threadIdx.x;
    int wid = tid >> 5, lane = tid & 31;
    float thr = fabsf(threshold[h]) * 0.1f;
    float lk  = sigmoidf_(leak[h]);
    float st  = softplusf_(steepness[h]);
    float rsp = softplusf_(ref_strength[h]);
    float cw  = sigmoidf_(cross_w[h]);
    float rinv = g_rowinv[r];
    size_t base = (size_t)r * TT;
    float mv[8];
    float sum = 0.0f;
    #pragma unroll
    for (int i = 0; i < 2; i++) {
        int k = i * 512 + tid * 4;
        if (k < nk) {
            float4 p4 = *(const float4*)&g_probs[base + k];
            float4 c4 = *(const float4*)&g_colsum[bh*TT + k];
            float4 f4 = *(const float4*)(refst + b*TT + k);
            float pp[4] = {p4.x, p4.y, p4.z, p4.w};
            float cc[4] = {c4.x, c4.y, c4.z, c4.w};
            float ff[4] = {f4.x, f4.y, f4.z, f4.w};
            #pragma unroll
            for (int j = 0; j < 4; j++) {
                float p = pp[j] * rinv;
                float eff = thr + rsp * cc[j] * (1.0f/1024.0f) + cw * ff[j];
                float fire = __fdividef(1.0f, 1.0f + __expf(-st * (p - eff)));
                float wgt = fire + lk * (1.0f - fire);
                float m = p * wgt;
                mv[i*4 + j] = m;
                sum += m;
            }
        } else {
            mv[i*4] = mv[i*4+1] = mv[i*4+2] = mv[i*4+3] = 0.0f;
        }
    }
    #pragma unroll
    for (int o = 16; o > 0; o >>= 1) sum += __shfl_xor_sync(0xffffffffu, sum, o);
    __shared__ float red[4];
    if (lane == 0) red[wid] = sum;
    __syncthreads();
    float invs = 1.0f / (red[0] + red[1] + red[2] + red[3] + 1e-8f);
    #pragma unroll
    for (int i = 0; i < 2; i++) {
        int k = i * 512 + tid * 4;
        if (k < nk) {
            float4 o4 = make_float4(mv[i*4]*invs, mv[i*4+1]*invs, mv[i*4+2]*invs, mv[i*4+3]*invs);
            *(float4*)&g_probs[base + k] = o4;
        }
    }
}

// ---------------------------------------------------------------------------
// y_pre = mod @ V (TF32 mma, hi/lo split, V pre-converted) + fused ref reduce
// ---------------------------------------------------------------------------
__global__ __launch_bounds__(128, 3)
void modv_kernel(float* __restrict__ refout) {
    int qt = (int)gridDim.x - 1 - (int)blockIdx.x;
    int bh = blockIdx.y;
    int b = bh >> 4, h = bh & 15;
    __shared__ float    Ms[64][68];
    __shared__ uint32_t VsH[64][68];
    __shared__ uint32_t VsL[64][68];
    int tid = threadIdx.x;
    int w = tid >> 5, lane = tid & 31;
    int g = lane >> 2, tig = lane & 3;

    float acc[8][4];
    #pragma unroll
    for (int nf = 0; nf < 8; nf++)
        #pragma unroll
        for (int i = 0; i < 4; i++) acc[nf][i] = 0.0f;

    for (int kt = 0; kt <= qt; kt++) {
        __syncthreads();
        {
            const float* msrc = g_probs + ((size_t)bh*TT + qt*64)*TT + kt*64;
            const float* vsrc = g_qkv + (size_t)(b*TT + kt*64)*C3 + 2*CC + h*HS;
            #pragma unroll
            for (int s = 0; s < 8; s++) {
                int f = tid + s*128;
                int row = f >> 4, c4 = f & 15;
                float4 mv = *(const float4*)(msrc + (size_t)row*TT + c4*4);
                *(float4*)&Ms[row][c4*4] = mv;
                float4 v = *(const float4*)(vsrc + (size_t)row*C3 + c4*4);
                uint32_t h0 = f2tf32(v.x), h1 = f2tf32(v.y), h2 = f2tf32(v.z), h3 = f2tf32(v.w);
                VsH[row][c4*4+0] = h0; VsH[row][c4*4+1] = h1;
                VsH[row][c4*4+2] = h2; VsH[row][c4*4+3] = h3;
                VsL[row][c4*4+0] = f2tf32(v.x - __uint_as_float(h0));
                VsL[row][c4*4+1] = f2tf32(v.y - __uint_as_float(h1));
                VsL[row][c4*4+2] = f2tf32(v.z - __uint_as_float(h2));
                VsL[row][c4*4+3] = f2tf32(v.w - __uint_as_float(h3));
            }
        }
        __syncthreads();

        // fused refractory column sums over this tile's 64 q rows
        if (tid < 64) {
            float s = 0.0f;
            #pragma unroll 8
            for (int i = 0; i < 64; i++) s += Ms[i][tid];
            atomicAdd(&refout[b*TT + kt*64 + tid], s * (1.0f / 16384.0f));
        }

        #pragma unroll
        for (int ks = 0; ks < 8; ks++) {
            uint32_t ah[4], al[4];
            #pragma unroll
            for (int i = 0; i < 4; i++) {
                float v = Ms[w*16 + g + (i & 1)*8][ks*8 + tig + (i >> 1)*4];
                uint32_t hi = f2tf32(v);
                ah[i] = hi;
                al[i] = f2tf32(v - __uint_as_float(hi));
            }
            #pragma unroll
            for (int nf = 0; nf < 8; nf++) {
                uint32_t b0h = VsH[ks*8 + tig][nf*8 + g];
                uint32_t b1h = VsH[ks*8 + tig + 4][nf*8 + g];
                uint32_t b0l = VsL[ks*8 + tig][nf*8 + g];
                uint32_t b1l = VsL[ks*8 + tig + 4][nf*8 + g];
                mma_tf32(acc[nf], ah, b0h, b1h);
                mma_tf32(acc[nf], ah, b0l, b1l);
                mma_tf32(acc[nf], al, b0h, b1h);
            }
        }
    }

    #pragma unroll
    for (int nf = 0; nf < 8; nf++) {
        int row = qt*64 + w*16 + g;
        int col = nf*8 + tig*2;
        float* dst = g_ypre + (size_t)(b*TT + row)*CC + h*HS + col;
        *(float2*)dst            = make_float2(acc[nf][0], acc[nf][1]);
        *(float2*)(dst + 8*CC)   = make_float2(acc[nf][2], acc[nf][3]);
    }
}

// ---------------------------------------------------------------------------
extern "C" void kernel_launch(void* const* d_in, const int* in_sizes, int n_in,
                              void* d_out, int out_size) {
    const float* x      = (const float*)d_in[0];
    const float* refst  = (const float*)d_in[1];
    const float* W_attn = (const float*)d_in[2];
    const float* b_attn = (const float*)d_in[3];
    const float* W_proj = (const float*)d_in[4];
    const float* b_proj = (const float*)d_in[5];
    const float* thr    = (const float*)d_in[6];
    const float* leak   = (const float*)d_in[7];
    const float* steep  = (const float*)d_in[8];
    const float* refstr = (const float*)d_in[9];
    const float* crossw = (const float*)d_in[10];

    float* y_out   = (float*)d_out;
    float* ref_out = (float*)d_out + (size_t)BB*TT*CC;

    float* qkv  = nullptr;  cudaGetSymbolAddress((void**)&qkv,  g_qkv);
    float* ypre = nullptr;  cudaGetSymbolAddress((void**)&ypre, g_ypre);

    init_kernel<<<(BHT*TT + 255)/256, 256>>>(ref_out);
    gemm_tf32_kernel<<<dim3(C3/128, (BB*TT)/128), 256>>>(x, W_attn, b_attn, qkv, BB*TT, C3, CC);
    scores_exp_kernel<<<dim3(TT/64, BHT), 128>>>();
    lifmod_kernel<<<NROWS, 128>>>(refst, thr, leak, steep, refstr, crossw);
    modv_kernel<<<dim3(TT/64, BHT), 128>>>(ref_out);
    gemm_tf32_kernel<<<dim3(CC/128, (BB*TT)/128), 256>>>(ypre, W_proj, b_proj, y_out, BB*TT, CC, CC);
}